// round 1
// baseline (speedup 1.0000x reference)
#include <cuda_runtime.h>
#include <math.h>

#define BB   4096
#define LMAX 5
#define TMAX 50
#define KS   65
#define KT   49
#define EPSF 1e-30f

// Per-batch partial log-likelihood scratch (no allocations allowed in kernel_launch).
__device__ float g_ll_part[BB];

__global__ __launch_bounds__(256, 8)
void mixalign_batch_kernel(const float* __restrict__ src_sent,
                           const float* __restrict__ trg_sent,
                           const float* __restrict__ src_bd,
                           const float* __restrict__ trg_bd,
                           float* __restrict__ out)   // out[0]=ll (written by reducer), out[1+b*T+t]=scales
{
    const int b    = blockIdx.x;
    const int tid  = threadIdx.x;
    const int warp = tid >> 5;
    const int lane = tid & 31;

    __shared__ float sTsum[TMAX];   // softmax row sums of trg rows
    __shared__ float sR[LMAX];      // softmax row sums of src rows
    __shared__ float sScales[TMAX];

    // ---- trg softmax row sums: one warp per row, 8 warps round-robin over 50 rows ----
    const float* trgb = trg_sent + (size_t)b * TMAX * KT;
    for (int t = warp; t < TMAX; t += 8) {
        const float* row = trgb + t * KT;
        float x0 = (lane      < KT) ? row[lane]      : -INFINITY;
        float x1 = (lane + 32 < KT) ? row[lane + 32] : -INFINITY;
        float m = fmaxf(x0, x1);
        #pragma unroll
        for (int o = 16; o; o >>= 1) m = fmaxf(m, __shfl_xor_sync(0xFFFFFFFFu, m, o));
        float e0 = (lane      < KT) ? expf(x0 - m) : 0.f;
        float e1 = (lane + 32 < KT) ? expf(x1 - m) : 0.f;
        float s = e0 + e1;
        #pragma unroll
        for (int o = 16; o; o >>= 1) s += __shfl_xor_sync(0xFFFFFFFFu, s, o);
        // row sum of softmax = sum of per-element divisions (match reference rounding shape)
        float p = e0 / s + e1 / s;
        #pragma unroll
        for (int o = 16; o; o >>= 1) p += __shfl_xor_sync(0xFFFFFFFFu, p, o);
        if (lane == 0) sTsum[t] = p;
    }

    // ---- src softmax row sums: warps 0..4, KS=65 -> 3 elems/lane (third only lane 0) ----
    if (warp < LMAX) {
        const float* row = src_sent + ((size_t)b * LMAX + warp) * KS;
        float x0 = row[lane];          // 0..31
        float x1 = row[lane + 32];     // 32..63
        float x2 = (lane == 0) ? row[64] : -INFINITY;
        float m = fmaxf(fmaxf(x0, x1), x2);
        #pragma unroll
        for (int o = 16; o; o >>= 1) m = fmaxf(m, __shfl_xor_sync(0xFFFFFFFFu, m, o));
        float e0 = expf(x0 - m);
        float e1 = expf(x1 - m);
        float e2 = (lane == 0) ? expf(x2 - m) : 0.f;
        float s = e0 + e1 + e2;
        #pragma unroll
        for (int o = 16; o; o >>= 1) s += __shfl_xor_sync(0xFFFFFFFFu, s, o);
        float p = e0 / s + e1 / s + e2 / s;
        #pragma unroll
        for (int o = 16; o; o >>= 1) p += __shfl_xor_sync(0xFFFFFFFFu, p, o);
        if (lane == 0) sR[warp] = p;
    }
    __syncthreads();

    // ---- Phase 2: reduced L-dim recursion + per-batch ll (thread 0; trivially small) ----
    if (tid == 0) {
        float mask[LMAX], Rl[LMAX], g[LMAX], initA[LMAX];
        float M = 0.f;
        #pragma unroll
        for (int l = 0; l < LMAX; ++l) {
            mask[l] = src_bd[(size_t)b * LMAX + l];
            Rl[l]   = sR[l];
            M += mask[l];
        }
        const float Linv = 1.f / fmaxf(M, 1.f);
        #pragma unroll
        for (int l = 0; l < LMAX; ++l) initA[l] = mask[l] * Linv;  // init == diag(A)

        // Z = sum_s prob_z = (sum_l mask*R) / sum_l mask   (no clamp in reference LL path)
        float Z = 0.f;
        #pragma unroll
        for (int l = 0; l < LMAX; ++l) Z += mask[l] * Rl[l];
        Z /= M;

        // log-likelihood partial: prob_x[t] = (Z/KT) * Tsum[t]
        const float* tb = trg_bd + (size_t)b * TMAX;
        const float pref = Z * (1.0f / (float)KT);
        float llb = 0.f;
        for (int t = 0; t < TMAX; ++t)
            llb += tb[t] * logf(fmaxf(pref * sTsum[t], EPSF));
        g_ll_part[b] = llb;

        // forward scales: c_t = Tsum[t]/KT (px is s-independent since P_st constant)
        const float c0 = sTsum[0] * (1.0f / (float)KT);
        float s0acc = 0.f;
        #pragma unroll
        for (int l = 0; l < LMAX; ++l) { g[l] = initA[l] * Rl[l]; s0acc += g[l]; }
        const float s0 = c0 * s0acc;
        sScales[0] = s0;
        {
            const float inv = c0 / fmaxf(s0, EPSF);
            #pragma unroll
            for (int l = 0; l < LMAX; ++l) g[l] *= inv;   // g = normalized per-l sums of f
        }
        for (int t = 1; t < TMAX; ++t) {
            const float ct = sTsum[t] * (1.0f / (float)KT);
            float G = 0.f;
            #pragma unroll
            for (int l = 0; l < LMAX; ++l) G += mask[l] * g[l];
            float raw[LMAX];
            float sc = 0.f;
            #pragma unroll
            for (int l = 0; l < LMAX; ++l) {
                const float diag_g = initA[l] * g[l];
                const float v = Linv * mask[l] * G - diag_g;    // (A_offdiag @ g)_l
                raw[l] = ct * (diag_g + v * Rl[l]);             // term1+term2 summed over s
                sc += raw[l];
            }
            sScales[t] = sc;
            const float is = 1.f / fmaxf(sc, EPSF);
            #pragma unroll
            for (int l = 0; l < LMAX; ++l) g[l] = raw[l] * is;
        }
    }
    __syncthreads();

    // ---- write scales (coalesced) ----
    if (tid < TMAX)
        out[1 + (size_t)b * TMAX + tid] = sScales[tid];
}

// Deterministic fixed-order reduction of the 4096 per-batch ll partials.
__global__ void mixalign_ll_reduce(float* __restrict__ out)
{
    __shared__ float s[1024];
    const int tid = threadIdx.x;
    float v = g_ll_part[tid] + g_ll_part[tid + 1024]
            + g_ll_part[tid + 2048] + g_ll_part[tid + 3072];
    s[tid] = v;
    __syncthreads();
    #pragma unroll
    for (int o = 512; o > 0; o >>= 1) {
        if (tid < o) s[tid] += s[tid + o];
        __syncthreads();
    }
    if (tid == 0) out[0] = s[0];
}

extern "C" void kernel_launch(void* const* d_in, const int* in_sizes, int n_in,
                              void* d_out, int out_size)
{
    const float* src_sent = (const float*)d_in[0];  // [B, L, KS]
    const float* trg_sent = (const float*)d_in[1];  // [B, T, KT]
    const float* src_bd   = (const float*)d_in[2];  // [B, L]
    const float* trg_bd   = (const float*)d_in[3];  // [B, T]
    float* out = (float*)d_out;                     // [1 + B*T]

    mixalign_batch_kernel<<<BB, 256>>>(src_sent, trg_sent, src_bd, trg_bd, out);
    mixalign_ll_reduce<<<1, 1024>>>(out);
}

// round 2
// speedup vs baseline: 2.9187x; 2.9187x over previous
#include <cuda_runtime.h>
#include <math.h>

#define BB   4096
#define LMAX 5
#define TMAX 50
#define KT   49
#define EPSF 1e-30f

// Per-batch partial log-likelihood scratch + completion counter (no allocs allowed).
__device__ float        g_ll_part[BB];
__device__ unsigned int g_done = 0;

// Algebraic simplification: softmax row sums are identically 1, so the outputs
// depend on src_sent/trg_sent only through rounding noise (O(1e-7)). We honor the
// boundary inputs exactly and substitute Tsum = R = 1.
__global__ __launch_bounds__(64, 16)
void mixalign_kernel(const float* __restrict__ src_bd,   // [B, L]
                     const float* __restrict__ trg_bd,   // [B, T]
                     float* __restrict__ out)            // [1 + B*T]
{
    const int b   = blockIdx.x;
    const int tid = threadIdx.x;

    __shared__ float sScales[TMAX];
    __shared__ float sRed[2];

    // ---- Σ_t trg_boundary[b,t] : warp 0 covers 0..31, warp 1 covers 32..49 ----
    float tbv = 0.f;
    if (tid < TMAX) tbv = trg_bd[(size_t)b * TMAX + tid];
    {
        float s = tbv;
        #pragma unroll
        for (int o = 16; o; o >>= 1) s += __shfl_xor_sync(0xFFFFFFFFu, s, o);
        if ((tid & 31) == 0) sRed[tid >> 5] = s;
    }
    __syncthreads();

    // ---- thread 0: tiny 5-dim recursion (R = 1, ct = 1/KT) ----
    if (tid == 0) {
        const float Stb = sRed[0] + sRed[1];

        float mask[LMAX], initA[LMAX], g[LMAX];
        float M = 0.f;
        #pragma unroll
        for (int l = 0; l < LMAX; ++l) {
            mask[l] = src_bd[(size_t)b * LMAX + l];
            M += mask[l];
        }
        const float Linv = 1.f / fmaxf(M, 1.f);
        #pragma unroll
        for (int l = 0; l < LMAX; ++l) initA[l] = mask[l] * Linv;  // init == diag(A)

        // Z = (Σ mask·R)/max(M,1) with R=1
        float Z = 0.f;
        #pragma unroll
        for (int l = 0; l < LMAX; ++l) Z += initA[l];

        // log-likelihood partial: prob_x[t] = Z/KT for all t
        g_ll_part[b] = Stb * logf(fmaxf(Z * (1.0f / (float)KT), EPSF));

        // forward scales, ct = 1/KT each step
        const float ct = 1.0f / (float)KT;
        float s0 = 0.f;
        #pragma unroll
        for (int l = 0; l < LMAX; ++l) { g[l] = initA[l]; s0 += g[l]; }
        s0 *= ct;
        sScales[0] = s0;
        {
            const float inv = ct / fmaxf(s0, EPSF);
            #pragma unroll
            for (int l = 0; l < LMAX; ++l) g[l] *= inv;
        }
        for (int t = 1; t < TMAX; ++t) {
            float G = 0.f;
            #pragma unroll
            for (int l = 0; l < LMAX; ++l) G += mask[l] * g[l];
            float raw[LMAX], sc = 0.f;
            #pragma unroll
            for (int l = 0; l < LMAX; ++l) {
                const float diag_g = initA[l] * g[l];
                // term1 + term2 (R=1): diag_g + (Linv*mask*G - diag_g)*1 = Linv*mask*G
                raw[l] = ct * (Linv * mask[l] * G);
                sc += raw[l];
                (void)diag_g;
            }
            sScales[t] = sc;
            const float is = 1.f / fmaxf(sc, EPSF);
            #pragma unroll
            for (int l = 0; l < LMAX; ++l) g[l] = raw[l] * is;
        }
    }
    __syncthreads();

    // ---- coalesced scale writes ----
    if (tid < TMAX)
        out[1 + (size_t)b * TMAX + tid] = sScales[tid];

    // ---- last-block deterministic fixed-order reduction of ll partials ----
    __shared__ unsigned int sIsLast;
    if (tid == 0) {
        __threadfence();
        sIsLast = (atomicAdd(&g_done, 1u) == BB - 1u);
    }
    __syncthreads();
    if (sIsLast) {
        __shared__ float sAcc[64];
        float v = 0.f;
        #pragma unroll
        for (int i = 0; i < BB / 64; ++i)        // fixed order per thread
            v += g_ll_part[tid + 64 * i];
        sAcc[tid] = v;
        __syncthreads();
        #pragma unroll
        for (int o = 32; o > 0; o >>= 1) {       // fixed-order tree
            if (tid < o) sAcc[tid] += sAcc[tid + o];
            __syncthreads();
        }
        if (tid == 0) {
            out[0] = sAcc[0];
            g_done = 0;                          // reset for next graph replay
        }
    }
}

extern "C" void kernel_launch(void* const* d_in, const int* in_sizes, int n_in,
                              void* d_out, int out_size)
{
    const float* src_bd = (const float*)d_in[2];  // [B, L]
    const float* trg_bd = (const float*)d_in[3];  // [B, T]
    float* out = (float*)d_out;                   // [1 + B*T]

    mixalign_kernel<<<BB, 64>>>(src_bd, trg_bd, out);
}

// round 3
// speedup vs baseline: 8.0786x; 2.7679x over previous
#include <cuda_runtime.h>
#include <math.h>

#define BB   4096
#define LMAX 5
#define TMAX 50
#define KT   49
#define EPSF 1e-30f
#define WPB  16                      // warps per block
#define NBLK (BB / WPB)              // 256 blocks

__device__ float        g_ll_blk[NBLK];
__device__ unsigned int g_done = 0;

// Closed-form solution:
//   softmax row sums == 1 (exactly, in exact arithmetic), so with P_st = 1/KT:
//     s0   = ct * S,           S = Linv*M,  Linv = 1/max(M,1),  M = sum(mask)
//     sc_1 = ct * Linv^2 * M * Q / S,       Q = sum(mask^2)
//     sc_t = ct * Linv * Q   (t >= 2; g[l]=mask[l]/M is the recursion fixed point)
//   ll   = (sum_t tb) * log(max((M/M')/KT, EPS)),  M' = M (reference divides by raw sum)
__global__ __launch_bounds__(512, 4)
void mixalign_closed_kernel(const float* __restrict__ src_bd,   // [B, L]
                            const float* __restrict__ trg_bd,   // [B, T]
                            float* __restrict__ out)            // [1 + B*T]
{
    const int tid  = threadIdx.x;
    const int w    = tid >> 5;
    const int lane = tid & 31;
    const int b    = blockIdx.x * WPB + w;

    __shared__ float sLL[WPB];

    // ---- per-batch mask stats: M = sum(mask), Q = sum(mask^2) ----
    float mk = (lane < LMAX) ? src_bd[(size_t)b * LMAX + lane] : 0.f;
    float M = mk, Q = mk * mk;
    #pragma unroll
    for (int o = 16; o; o >>= 1) {
        M += __shfl_xor_sync(0xFFFFFFFFu, M, o);
        Q += __shfl_xor_sync(0xFFFFFFFFu, Q, o);
    }

    const float ct   = 1.0f / (float)KT;
    const float Linv = 1.f / fmaxf(M, 1.f);
    const float S    = Linv * M;
    const float s0   = ct * S;
    const float sc1  = ct * Linv * Linv * M * Q / fmaxf(S, EPSF);
    const float scc  = ct * Linv * Q;

    // ---- Stb = sum_t trg_boundary[b,t] ----
    const float* tbp = trg_bd + (size_t)b * TMAX;
    float tb0 = tbp[lane];
    float tb1 = (lane + 32 < TMAX) ? tbp[lane + 32] : 0.f;
    float Stb = tb0 + tb1;
    #pragma unroll
    for (int o = 16; o; o >>= 1) Stb += __shfl_xor_sync(0xFFFFFFFFu, Stb, o);

    // ---- scales: t=0 -> s0, t=1 -> sc1, t>=2 -> scc ----
    float* ob = out + 1 + (size_t)b * TMAX;
    ob[lane] = (lane == 0) ? s0 : (lane == 1 ? sc1 : scc);
    if (lane + 32 < TMAX) ob[lane + 32] = scc;

    // ---- per-batch ll partial (reference ll path divides by raw M, no clamp) ----
    if (lane == 0) {
        const float Z = M / fmaxf(M, EPSF);
        sLL[w] = Stb * logf(fmaxf(Z * ct, EPSF));
    }
    __syncthreads();

    // ---- per-block fixed-order partial ----
    __shared__ unsigned int sIsLast;
    if (tid == 0) {
        float acc = 0.f;
        #pragma unroll
        for (int i = 0; i < WPB; ++i) acc += sLL[i];
        g_ll_blk[blockIdx.x] = acc;
        __threadfence();
        sIsLast = (atomicAdd(&g_done, 1u) == NBLK - 1u);
    }
    __syncthreads();

    // ---- last block: deterministic tree over 256 block partials ----
    if (sIsLast) {
        __shared__ float sAcc[NBLK];
        if (tid < NBLK) sAcc[tid] = g_ll_blk[tid];
        __syncthreads();
        #pragma unroll
        for (int o = NBLK / 2; o > 0; o >>= 1) {
            if (tid < o) sAcc[tid] += sAcc[tid + o];
            __syncthreads();
        }
        if (tid == 0) {
            out[0] = sAcc[0];
            g_done = 0;                     // reset for next graph replay
        }
    }
}

extern "C" void kernel_launch(void* const* d_in, const int* in_sizes, int n_in,
                              void* d_out, int out_size)
{
    const float* src_bd = (const float*)d_in[2];  // [B, L]
    const float* trg_bd = (const float*)d_in[3];  // [B, T]
    float* out = (float*)d_out;                   // [1 + B*T]

    mixalign_closed_kernel<<<NBLK, 512>>>(src_bd, trg_bd, out);
}

// round 4
// speedup vs baseline: 8.8359x; 1.0938x over previous
#include <cuda_runtime.h>
#include <math.h>

#define BB     4096
#define LMAX   5
#define TMAX   50
#define EPSF   1e-30f
#define WPB    16                     // warps per block (16 batches/block)
#define NBLK   (BB / WPB)             // 256 blocks
#define LOG_CT (-3.8918202981106265f) // log(1/49), exact to float
#define FPSCAL 4294967296.0           // 2^32 fixed-point scale

__device__ unsigned long long g_acc  = 0ull;  // Q32 fixed-point ll accumulator
__device__ unsigned int       g_done = 0;

// Closed form (softmax row sums == 1):
//   scales: s0 = ct*S, sc1 = ct*Linv^2*M*Q/S, sc_t = ct*Linv*Q (t>=2)
//           with M = sum(mask), Q = sum(mask^2), Linv = 1/max(M,1), S = Linv*M
//   ll    = log(1/49) * sum(trg_boundary)   (Z = M/M == 1 exactly in IEEE fp)
__global__ __launch_bounds__(512, 4)
void mixalign_kernel(const float* __restrict__ src_bd,   // [B, L]
                     const float* __restrict__ trg_bd,   // [B, T]
                     float* __restrict__ out)            // [1 + B*T]
{
    const int tid  = threadIdx.x;
    const int w    = tid >> 5;
    const int lane = tid & 31;
    const int b    = blockIdx.x * WPB + w;

    __shared__ float sStb[WPB];

    // ---- mask stats: lanes 0..4 hold mask; 3 xor rounds over the 8-lane group ----
    float mk = (lane < LMAX) ? src_bd[(size_t)b * LMAX + lane] : 0.f;
    float M = mk, Q = mk * mk;
    #pragma unroll
    for (int o = 4; o; o >>= 1) {
        M += __shfl_xor_sync(0xFFFFFFFFu, M, o);
        Q += __shfl_xor_sync(0xFFFFFFFFu, Q, o);
    }
    M = __shfl_sync(0xFFFFFFFFu, M, 0);
    Q = __shfl_sync(0xFFFFFFFFu, Q, 0);

    const float ct   = 1.0f / 49.0f;
    const float Linv = 1.f / fmaxf(M, 1.f);
    const float S    = Linv * M;
    const float s0   = ct * S;
    const float sc1  = ct * Linv * Linv * M * Q / fmaxf(S, EPSF);
    const float scc  = ct * Linv * Q;

    // ---- Stb = sum_t trg_boundary[b,t] ----
    const float* tbp = trg_bd + (size_t)b * TMAX;
    float Stb = tbp[lane] + ((lane + 32 < TMAX) ? tbp[lane + 32] : 0.f);
    #pragma unroll
    for (int o = 16; o; o >>= 1) Stb += __shfl_xor_sync(0xFFFFFFFFu, Stb, o);
    if (lane == 0) sStb[w] = Stb;

    // ---- scales (coalesced) ----
    float* ob = out + 1 + (size_t)b * TMAX;
    ob[lane] = (lane == 0) ? s0 : (lane == 1 ? sc1 : scc);
    if (lane + 32 < TMAX) ob[lane + 32] = scc;

    __syncthreads();

    // ---- tail: order-independent (deterministic) fixed-point accumulation ----
    if (tid == 0) {
        float acc = 0.f;
        #pragma unroll
        for (int i = 0; i < WPB; ++i) acc += sStb[i];
        const long long q = (long long)((double)acc * FPSCAL);
        atomicAdd(&g_acc, (unsigned long long)q);
        __threadfence();
        if (atomicAdd(&g_done, 1u) == NBLK - 1u) {
            __threadfence();
            const unsigned long long a = atomicAdd(&g_acc, 0ull);  // L2-coherent read
            out[0] = (float)((double)(long long)a * (1.0 / FPSCAL)) * LOG_CT;
            g_acc  = 0ull;   // reset for next graph replay
            g_done = 0;
        }
    }
}

extern "C" void kernel_launch(void* const* d_in, const int* in_sizes, int n_in,
                              void* d_out, int out_size)
{
    const float* src_bd = (const float*)d_in[2];  // [B, L]
    const float* trg_bd = (const float*)d_in[3];  // [B, T]
    float* out = (float*)d_out;                   // [1 + B*T]

    mixalign_kernel<<<NBLK, 512>>>(src_bd, trg_bd, out);
}

// round 5
// speedup vs baseline: 9.7500x; 1.1034x over previous
#include <cuda_runtime.h>
#include <math.h>

#define BB     4096
#define LMAX   5
#define TMAX   50
#define WPB    32                     // batches (=warps) per block
#define NBLK   (BB / WPB)             // 128 blocks
#define NTHR   (WPB * 32)             // 1024 threads
#define LOG_CT (-3.8918202981106265f) // log(1/49)
#define FPSCAL 4294967296.0           // 2^32 fixed-point scale

__device__ unsigned long long g_acc  = 0ull;  // Q32 fixed-point sum(trg_bd)
__device__ unsigned int       g_done = 0;

// Closed form (softmax row sums == 1; P_st = 1/49):
//   M = sum(mask), Q = sum(mask^2), Linv = 1/max(M,1)
//   scales: t=0 -> ct*Linv*M ; t>=1 -> ct*Linv*Q   (recursion fixed point)
//   ll = log(1/49) * sum(trg_boundary)              (Z = M/M == 1)
__global__ __launch_bounds__(NTHR, 1)
void mixalign_kernel(const float* __restrict__ src_bd,   // [B, L]
                     const float* __restrict__ trg_bd,   // [B, T]
                     float* __restrict__ out)            // [1 + B*T]
{
    const int tid  = threadIdx.x;
    const int w    = tid >> 5;
    const int lane = tid & 31;
    const int b    = blockIdx.x * WPB + w;

    __shared__ float sWp[WPB];

    // ---- coalesced trg_bd sweep: block's contiguous 1600-float slice ----
    const float* tbp = trg_bd + (size_t)blockIdx.x * (WPB * TMAX);
    float v = tbp[tid] + ((tid < WPB * TMAX - NTHR) ? tbp[tid + NTHR] : 0.f);

    // ---- per-batch mask stats (lanes 0..4 active; 3 xor rounds cover 8-lane group) ----
    float mk = (lane < LMAX) ? src_bd[(size_t)b * LMAX + lane] : 0.f;
    float M = mk, Q = mk * mk;
    #pragma unroll
    for (int o = 4; o; o >>= 1) {
        M += __shfl_xor_sync(0xFFFFFFFFu, M, o);
        Q += __shfl_xor_sync(0xFFFFFFFFu, Q, o);
    }
    M = __shfl_sync(0xFFFFFFFFu, M, 0);
    Q = __shfl_sync(0xFFFFFFFFu, Q, 0);

    const float ct   = 1.0f / 49.0f;
    const float Linv = __fdividef(1.f, fmaxf(M, 1.f));
    const float s0   = ct * (Linv * M);
    const float scc  = ct * (Linv * Q);   // == sc1 algebraically

    // ---- scale stores (coalesced within warp) ----
    float* ob = out + 1 + (size_t)b * TMAX;
    ob[lane] = lane ? scc : s0;
    if (lane + 32 < TMAX) ob[lane + 32] = scc;

    // ---- warp-reduce the tb partial, then one 32-wide final reduce ----
    #pragma unroll
    for (int o = 16; o; o >>= 1) v += __shfl_xor_sync(0xFFFFFFFFu, v, o);
    if (lane == 0) sWp[w] = v;
    __syncthreads();

    if (w == 0) {
        float x = sWp[lane];
        #pragma unroll
        for (int o = 16; o; o >>= 1) x += __shfl_xor_sync(0xFFFFFFFFu, x, o);
        if (lane == 0) {
            // order-independent (deterministic) Q32 fixed-point accumulation
            const long long q = (long long)((double)x * FPSCAL);
            atomicAdd(&g_acc, (unsigned long long)q);
            __threadfence();
            if (atomicAdd(&g_done, 1u) == NBLK - 1u) {
                __threadfence();
                const unsigned long long a = atomicAdd(&g_acc, 0ull);
                out[0] = (float)((double)(long long)a * (1.0 / FPSCAL)) * LOG_CT;
                g_acc  = 0ull;   // reset for next graph replay
                g_done = 0;
            }
        }
    }
}

extern "C" void kernel_launch(void* const* d_in, const int* in_sizes, int n_in,
                              void* d_out, int out_size)
{
    const float* src_bd = (const float*)d_in[2];  // [B, L]
    const float* trg_bd = (const float*)d_in[3];  // [B, T]
    float* out = (float*)d_out;                   // [1 + B*T]

    mixalign_kernel<<<NBLK, NTHR>>>(src_bd, trg_bd, out);
}

// round 6
// speedup vs baseline: 10.3761x; 1.0642x over previous
#include <cuda_runtime.h>
#include <math.h>

#define BB     4096
#define LMAX   5
#define TMAX   50
#define WPB    32                     // batches (=warps) per block
#define NBLK   (BB / WPB)             // 128 blocks
#define NTHR   (WPB * 32)             // 1024 threads
#define LOG_CT (-3.8918202981106265f) // log(1/49)
#define Q20    1048576.0              // 2^20 fixed-point scale
#define BIAS   4294967296ll           // 2^32 per-block bias (keeps packed field >= 0)

// Packed accumulator: bits[0:8) = arrival count, bits[8:64) = sum of biased Q20 partials.
__device__ unsigned long long g_acc = 0ull;

// Closed form (softmax row sums == 1; P_st = 1/49):
//   M = sum(mask), Q = sum(mask^2), Linv = 1/max(M,1)
//   scales: t=0 -> ct*Linv*M ; t>=1 -> ct*Linv*Q   (recursion fixed point)
//   ll = log(1/49) * sum(trg_boundary)              (Z = M/M == 1 exactly)
__global__ __launch_bounds__(NTHR, 1)
void mixalign_kernel(const float* __restrict__ src_bd,   // [B, L]
                     const float* __restrict__ trg_bd,   // [B, T]
                     float* __restrict__ out)            // [1 + B*T]
{
    const int tid  = threadIdx.x;
    const int w    = tid >> 5;
    const int lane = tid & 31;
    const int b    = blockIdx.x * WPB + w;

    __shared__ float sWp[WPB];

    // ---- block's contiguous 1600-float trg_bd slice: 400 float4 loads ----
    const float4* tb4 = (const float4*)(trg_bd + (size_t)blockIdx.x * (WPB * TMAX));
    float v = 0.f;
    if (tid < (WPB * TMAX) / 4) {
        const float4 t4 = tb4[tid];
        v = (t4.x + t4.y) + (t4.z + t4.w);
    }

    // ---- per-batch mask stats (lanes 0..4 active; 3 xor rounds cover 8-lane group) ----
    float mk = (lane < LMAX) ? src_bd[(size_t)b * LMAX + lane] : 0.f;
    float M = mk, Q = mk * mk;
    #pragma unroll
    for (int o = 4; o; o >>= 1) {
        M += __shfl_xor_sync(0xFFFFFFFFu, M, o);
        Q += __shfl_xor_sync(0xFFFFFFFFu, Q, o);
    }
    M = __shfl_sync(0xFFFFFFFFu, M, 0);
    Q = __shfl_sync(0xFFFFFFFFu, Q, 0);

    const float ct   = 1.0f / 49.0f;
    const float Linv = __fdividef(1.f, fmaxf(M, 1.f));
    const float s0   = ct * (Linv * M);
    const float scc  = ct * (Linv * Q);   // sc1 == scc algebraically

    // ---- scale stores (coalesced within warp) ----
    float* ob = out + 1 + (size_t)b * TMAX;
    ob[lane] = lane ? scc : s0;
    if (lane + 32 < TMAX) ob[lane + 32] = scc;

    // ---- block-level sum of the trg partial ----
    #pragma unroll
    for (int o = 16; o; o >>= 1) v += __shfl_xor_sync(0xFFFFFFFFu, v, o);
    if (lane == 0) sWp[w] = v;
    __syncthreads();

    if (w == 0) {
        float x = sWp[lane];
        #pragma unroll
        for (int o = 16; o; o >>= 1) x += __shfl_xor_sync(0xFFFFFFFFu, x, o);
        if (lane == 0) {
            // ONE atomic per block: counter in low 8 bits, biased Q20 sum above.
            const long long qb = (long long)llrint((double)x * Q20) + BIAS;
            const unsigned long long pack = ((unsigned long long)qb << 8) | 1ull;
            const unsigned long long old  = atomicAdd(&g_acc, pack);
            if ((old & 0xFFull) == (unsigned long long)(NBLK - 1)) {
                // we are the last arrival; old+pack holds the complete packed total
                const long long tot = (long long)((old + pack) >> 8) - (long long)NBLK * BIAS;
                out[0] = (float)((double)tot * (1.0 / Q20)) * LOG_CT;
                g_acc = 0ull;                 // reset for next graph replay
            }
        }
    }
}

extern "C" void kernel_launch(void* const* d_in, const int* in_sizes, int n_in,
                              void* d_out, int out_size)
{
    const float* src_bd = (const float*)d_in[2];  // [B, L]
    const float* trg_bd = (const float*)d_in[3];  // [B, T]
    float* out = (float*)d_out;                   // [1 + B*T]

    mixalign_kernel<<<NBLK, NTHR>>>(src_bd, trg_bd, out);
}

// round 7
// speedup vs baseline: 11.7202x; 1.1295x over previous
#include <cuda_runtime.h>
#include <math.h>

#define BB     4096
#define LMAX   5
#define TMAX   50
#define WPB    32                     // batches (=warps) per block
#define NBLK   (BB / WPB)             // 128 blocks
#define NTHR   (WPB * 32)             // 1024 threads
#define NV4    ((WPB * TMAX) / 4)     // 400 float4 loads per block
#define NWV    ((NV4 + 31) / 32)      // 13 warps carry trg partials
#define LOG_CT (-3.8918202981106265f) // log(1/49)
#define Q20    1048576.0              // 2^20 fixed-point scale
#define BIAS   4294967296ll           // 2^32 per-block bias (keeps packed field >= 0)

// Packed accumulator: bits[0:8) = arrival count, bits[8:64) = sum of biased Q20 partials.
__device__ unsigned long long g_acc = 0ull;

// Closed form (softmax row sums == 1; P_st = 1/49):
//   M = sum(mask), Q = sum(mask^2), Linv = 1/max(M,1)
//   scales: t=0 -> ct*Linv*M ; t>=1 -> ct*Linv*Q   (recursion fixed point)
//   ll = log(1/49) * sum(trg_boundary)              (Z = M/M == 1 exactly)
__global__ __launch_bounds__(NTHR, 1)
void mixalign_kernel(const float* __restrict__ src_bd,   // [B, L]
                     const float* __restrict__ trg_bd,   // [B, T]
                     float* __restrict__ out)            // [1 + B*T]
{
    const int tid  = threadIdx.x;
    const int w    = tid >> 5;
    const int lane = tid & 31;
    const int b    = blockIdx.x * WPB + w;

    __shared__ float sWp[NWV];

    // ---- trg_bd slice: 400 float4 loads (warps 0..12), issued first for MLP ----
    float v = 0.f;
    if (tid < NV4) {
        const float4 t4 =
            ((const float4*)(trg_bd + (size_t)blockIdx.x * (WPB * TMAX)))[tid];
        v = (t4.x + t4.y) + (t4.z + t4.w);
    }

    // ---- per-batch mask stats: same-address broadcast loads, no shuffles ----
    const float* mrow = src_bd + (size_t)b * LMAX;
    const float m0 = mrow[0], m1 = mrow[1], m2 = mrow[2], m3 = mrow[3], m4 = mrow[4];
    const float M = ((m0 + m1) + (m2 + m3)) + m4;
    const float Q = ((m0 * m0 + m1 * m1) + (m2 * m2 + m3 * m3)) + m4 * m4;

    const float ct   = 1.0f / 49.0f;
    const float Linv = __fdividef(1.f, fmaxf(M, 1.f));
    const float s0   = ct * (Linv * M);
    const float scc  = ct * (Linv * Q);   // sc1 == scc algebraically

    // ---- scale stores (coalesced within warp) ----
    float* ob = out + 1 + (size_t)b * TMAX;
    ob[lane] = lane ? scc : s0;
    if (lane + 32 < TMAX) ob[lane + 32] = scc;

    // ---- trg partial: warp reduce (warps 0..12 only), then 13-wide final ----
    if (w < NWV) {
        #pragma unroll
        for (int o = 16; o; o >>= 1) v += __shfl_xor_sync(0xFFFFFFFFu, v, o);
        if (lane == 0) sWp[w] = v;
    }
    __syncthreads();

    if (w == 0) {
        float x = (lane < NWV) ? sWp[lane] : 0.f;
        #pragma unroll
        for (int o = 8; o; o >>= 1) x += __shfl_xor_sync(0xFFFFFFFFu, x, o);
        if (lane == 0) {
            // ONE atomic per block: counter in low 8 bits, biased Q20 sum above.
            const long long qb = (long long)llrint((double)x * Q20) + BIAS;
            const unsigned long long pack = ((unsigned long long)qb << 8) | 1ull;
            const unsigned long long old  = atomicAdd(&g_acc, pack);
            if ((old & 0xFFull) == (unsigned long long)(NBLK - 1)) {
                // last arrival: old+pack holds the complete packed total
                const long long tot = (long long)((old + pack) >> 8) - (long long)NBLK * BIAS;
                out[0] = (float)((double)tot * (1.0 / Q20)) * LOG_CT;
                g_acc = 0ull;                 // reset for next graph replay
            }
        }
    }
}

extern "C" void kernel_launch(void* const* d_in, const int* in_sizes, int n_in,
                              void* d_out, int out_size)
{
    const float* src_bd = (const float*)d_in[2];  // [B, L]
    const float* trg_bd = (const float*)d_in[3];  // [B, T]
    float* out = (float*)d_out;                   // [1 + B*T]

    mixalign_kernel<<<NBLK, NTHR>>>(src_bd, trg_bd, out);
}